// round 14
// baseline (speedup 1.0000x reference)
#include <cuda_runtime.h>
#include <cstdint>

#define B_   4
#define T_   2048
#define C_   256
#define H_   8
#define HD_  32
#define C3_  768

// ---- fp16 scratch (module-load allocated; legal under no-alloc rules) ------
__device__ uint32_t g_x16u  [8192 * 128];   // x packed fp16    [8192][256]
__device__ uint32_t g_wqkv16u[128 * 768];   // w_qkv k-pair-packed [128][768]
__device__ uint32_t g_wp16u [128 * 256];    // w_proj k-pair-packed [128][256]
__device__ uint32_t g_qkv16u[8192 * 384];   // qkv fp16 (q pre-scaled) [8192][768]
__device__ uint32_t g_y16u  [8192 * 128];   // attention out fp16 [8192][256]

// ---- helpers ---------------------------------------------------------------
__device__ __forceinline__ uint32_t pack_f16x2(float lo, float hi) {
    uint32_t r; asm("cvt.rn.f16x2.f32 %0, %1, %2;" : "=r"(r) : "f"(hi), "f"(lo));
    return r;
}
__device__ __forceinline__ uint32_t ex2_h2(uint32_t x) {
    uint32_t y; asm("ex2.approx.f16x2 %0, %1;" : "=r"(y) : "r"(x)); return y;
}
__device__ __forceinline__ void mma_f16(float& c0, float& c1, float& c2, float& c3,
                                        uint32_t a0, uint32_t a1, uint32_t a2, uint32_t a3,
                                        uint32_t b0, uint32_t b1) {
    asm volatile("mma.sync.aligned.m16n8k16.row.col.f32.f16.f16.f32 "
                 "{%0,%1,%2,%3}, {%4,%5,%6,%7}, {%8,%9}, {%0,%1,%2,%3};"
                 : "+f"(c0), "+f"(c1), "+f"(c2), "+f"(c3)
                 : "r"(a0), "r"(a1), "r"(a2), "r"(a3), "r"(b0), "r"(b1));
}
__device__ __forceinline__ void ldm_x4(uint32_t& r0, uint32_t& r1, uint32_t& r2,
                                       uint32_t& r3, uint32_t saddr) {
    asm volatile("ldmatrix.sync.aligned.m8n8.x4.shared.b16 {%0,%1,%2,%3}, [%4];"
                 : "=r"(r0), "=r"(r1), "=r"(r2), "=r"(r3) : "r"(saddr));
}
__device__ __forceinline__ void ldm_x4t(uint32_t& r0, uint32_t& r1, uint32_t& r2,
                                        uint32_t& r3, uint32_t saddr) {
    asm volatile("ldmatrix.sync.aligned.m8n8.x4.trans.shared.b16 {%0,%1,%2,%3}, [%4];"
                 : "=r"(r0), "=r"(r1), "=r"(r2), "=r"(r3) : "r"(saddr));
}
__device__ __forceinline__ void cp_async16(uint32_t saddr, const void* gptr) {
    asm volatile("cp.async.cg.shared.global [%0], [%1], 16;" :: "r"(saddr), "l"(gptr));
}
__device__ __forceinline__ void cp_commit() {
    asm volatile("cp.async.commit_group;");
}
template <int N>
__device__ __forceinline__ void cp_wait() {
    asm volatile("cp.async.wait_group %0;" :: "n"(N));
}

// ----------------------------------------------------------------------------
// Pack kernels
// ----------------------------------------------------------------------------
__global__ void pack_f32_to_f16(const float* __restrict__ in,
                                uint32_t* __restrict__ out, int n4)
{
    int i = blockIdx.x * blockDim.x + threadIdx.x;
    if (i < n4) {
        float4 v = ((const float4*)in)[i];
        uint2 o; o.x = pack_f16x2(v.x, v.y); o.y = pack_f16x2(v.z, v.w);
        ((uint2*)out)[i] = o;
    }
}

__global__ void pack_w_kpairs(const float* __restrict__ in,
                              uint32_t* __restrict__ out, int K, int N)
{
    int i = blockIdx.x * blockDim.x + threadIdx.x;
    int n4 = N >> 2;
    if (i < (K >> 1) * n4) {
        int kp = i / n4, c4 = (i - kp * n4) * 4;
        float4 a = *(const float4*)&in[(size_t)(2 * kp) * N + c4];
        float4 b = *(const float4*)&in[(size_t)(2 * kp + 1) * N + c4];
        uint4 o;
        o.x = pack_f16x2(a.x, b.x); o.y = pack_f16x2(a.y, b.y);
        o.z = pack_f16x2(a.z, b.z); o.w = pack_f16x2(a.w, b.w);
        *(uint4*)&out[(size_t)kp * N + c4] = o;
    }
}

// ----------------------------------------------------------------------------
// fp16 tensor-core GEMM, BK=32, 3-stage cp.async, A-frags via ldmatrix.x4.
// BM=128, BN=128, 8 warps (2m x 4n, 64x32 warp tile).  (R12, unchanged)
// ----------------------------------------------------------------------------
#define AST 20
#define WST 136
#define GA_WORDS (128 * AST)
#define GW_WORDS (16 * WST)
#define GSTAGES 3
#define GEMM_SMEM_BYTES (GSTAGES * (GA_WORDS + GW_WORDS) * 4)

template <int MODE>
__global__ __launch_bounds__(256, 2)
void gemm16_kernel(const uint32_t* __restrict__ Apk,
                   const uint32_t* __restrict__ Wpk,
                   const float* __restrict__ bias,
                   void* __restrict__ outp,
                   int M, int N, int K, float qsc)
{
    extern __shared__ uint32_t gsm[];
    uint32_t* Asm = gsm;
    uint32_t* Wsm = gsm + GSTAGES * GA_WORDS;

    const int tid  = threadIdx.x;
    const int wid  = tid >> 5;
    const int lane = tid & 31;
    const int g    = lane >> 2;
    const int tg   = lane & 3;
    const int lm   = lane >> 3;
    const int lr   = lane & 7;
    const int wm   = wid & 1;
    const int wn   = wid >> 1;

    const int bm = blockIdx.y * 128;
    const int bn = blockIdx.x * 128;
    const int Kp2 = K >> 1;

    const int a_row = tid >> 1;
    const int a_seg = (tid & 1) * 8;
    const int w_row = tid >> 4;
    const int w_seg = (tid & 15) * 8;

    const uint32_t sA = (uint32_t)__cvta_generic_to_shared(Asm);
    const uint32_t sW = (uint32_t)__cvta_generic_to_shared(Wsm);

    const uint32_t afrag_base =
        (uint32_t)((((lm & 1) * 8 + lr) * AST + (lm >> 1) * 4) * 4);

    const int nChunks = K >> 5;          // 8

    auto prefetch = [&](int st, int c) {
        const uint32_t sa = sA + (uint32_t)st * GA_WORDS * 4;
        const uint32_t sw = sW + (uint32_t)st * GW_WORDS * 4;
        const int kp0 = c * 16;
        cp_async16(sa + (uint32_t)(a_row * AST + a_seg) * 4,
                   Apk + (size_t)(bm + a_row) * Kp2 + kp0 + a_seg);
        cp_async16(sa + (uint32_t)(a_row * AST + a_seg + 4) * 4,
                   Apk + (size_t)(bm + a_row) * Kp2 + kp0 + a_seg + 4);
        cp_async16(sw + (uint32_t)(w_row * WST + w_seg) * 4,
                   Wpk + (size_t)(kp0 + w_row) * N + bn + w_seg);
        cp_async16(sw + (uint32_t)(w_row * WST + w_seg + 4) * 4,
                   Wpk + (size_t)(kp0 + w_row) * N + bn + w_seg + 4);
    };

    float acc[4][4][4];
#pragma unroll
    for (int r = 0; r < 4; r++)
#pragma unroll
        for (int c = 0; c < 4; c++)
#pragma unroll
            for (int i = 0; i < 4; i++) acc[r][c][i] = 0.f;

    prefetch(0, 0); cp_commit();
    prefetch(1, 1); cp_commit();

    for (int ch = 0; ch < nChunks; ch++) {
        if (ch + 1 < nChunks) cp_wait<1>(); else cp_wait<0>();
        __syncthreads();
        if (ch + 2 < nChunks) {
            prefetch((ch + 2) % GSTAGES, ch + 2);
            cp_commit();
        }

        const uint32_t Ab_s = sA + (uint32_t)((ch % GSTAGES) * GA_WORDS) * 4;
        const uint32_t* Wb = Wsm + (ch % GSTAGES) * GW_WORDS;

#pragma unroll
        for (int kk = 0; kk < 2; kk++) {
            uint32_t a[4][4];
#pragma unroll
            for (int r = 0; r < 4; r++) {
                ldm_x4(a[r][0], a[r][1], a[r][2], a[r][3],
                       Ab_s + afrag_base
                            + (uint32_t)(((wm * 64 + r * 16) * AST + kk * 8) * 4));
            }
            uint32_t bfr[4][2];
#pragma unroll
            for (int c = 0; c < 4; c++) {
                const int col = wn * 32 + c * 8 + g;
                bfr[c][0] = Wb[(kk * 8 + tg)     * WST + col];
                bfr[c][1] = Wb[(kk * 8 + tg + 4) * WST + col];
            }
#pragma unroll
            for (int r = 0; r < 4; r++)
#pragma unroll
                for (int c = 0; c < 4; c++)
                    mma_f16(acc[r][c][0], acc[r][c][1], acc[r][c][2], acc[r][c][3],
                            a[r][0], a[r][1], a[r][2], a[r][3], bfr[c][0], bfr[c][1]);
        }
    }

    // ---- epilogue ----
#pragma unroll
    for (int r = 0; r < 4; r++) {
        const int row0 = bm + wm * 64 + r * 16 + g;
#pragma unroll
        for (int c = 0; c < 4; c++) {
            const int col = bn + wn * 32 + c * 8 + 2 * tg;
            const float2 bb = *(const float2*)&bias[col];
            float v0 = acc[r][c][0] + bb.x, v1 = acc[r][c][1] + bb.y;
            float v2 = acc[r][c][2] + bb.x, v3 = acc[r][c][3] + bb.y;
            if (MODE == 1) {
                const float sc = (col < C_) ? qsc : 1.f;
                uint32_t* o16 = (uint32_t*)outp;
                o16[(size_t)row0       * (N >> 1) + (col >> 1)] = pack_f16x2(v0 * sc, v1 * sc);
                o16[(size_t)(row0 + 8) * (N >> 1) + (col >> 1)] = pack_f16x2(v2 * sc, v3 * sc);
            } else {
                float* o32 = (float*)outp;
                *(float2*)&o32[(size_t)row0 * N + col]       = make_float2(v0, v1);
                *(float2*)&o32[(size_t)(row0 + 8) * N + col] = make_float2(v2, v3);
            }
        }
    }
}

// ----------------------------------------------------------------------------
// Causal flash attention, all-fp16 mma, no-max softmax, ldmatrix frags.
// R14: 128 q-rows per block (256 threads, 8 warps x 16 rows) — halves K/V
// gmem/L2 traffic, Q-load work, and per-row barrier overhead vs 64-row blocks.
// Per-warp compute skip for tiles fully above the warp's diagonal.
// ----------------------------------------------------------------------------
#define QST 20
#define KV_TILE (64 * QST)
#define Q_TILE  (128 * QST)
#define ATTN_SMEM_BYTES ((Q_TILE + 4 * KV_TILE) * 4)    // 30720 B
#define ONES_H2 0x3C003C00u

__global__ __launch_bounds__(256, 2)
void attn_kernel(const uint32_t* __restrict__ qkv, uint32_t* __restrict__ yout)
{
    extern __shared__ uint32_t sm[];
    uint32_t* Qp = sm;                      // 128 x 20
    uint32_t* Kp = sm + Q_TILE;             // [2][64 x 20]
    uint32_t* Vp = Kp + 2 * KV_TILE;        // [2][64 x 20]

    const int tid  = threadIdx.x;
    const int wid  = tid >> 5;              // 0..7
    const int lane = tid & 31;
    const int g    = lane >> 2;
    const int tg   = lane & 3;
    const int lm   = lane >> 3;
    const int lr   = lane & 7;

    const int qt = gridDim.x - 1 - blockIdx.x;   // heavy blocks first
    const int q0 = qt * 128;
    const int bh = blockIdx.y;
    const int b  = bh >> 3;
    const int h  = bh & 7;

    const uint32_t sQ = (uint32_t)__cvta_generic_to_shared(Qp);
    const uint32_t sK = (uint32_t)__cvta_generic_to_shared(Kp);
    const uint32_t sV = (uint32_t)__cvta_generic_to_shared(Vp);

    const uint32_t kfrag_base =
        (uint32_t)(((((lm >> 1) * 8) + lr) * QST + (lm & 1) * 4) * 4);
    const uint32_t vfrag_base =
        (uint32_t)(((((lm & 1) * 8) + lr) * QST + (lm >> 1) * 4) * 4);

    const uint32_t* base = qkv + (size_t)(b * T_) * 384;

    // K/V tile: 64 rows x 16 u32 each -> 512 float4 total; 256 thr x 2 iters
    auto prefetch_kv = [&](int buf, int kt) {
#pragma unroll
        for (int it = 0; it < 2; it++) {
            const int idx  = tid + it * 256;
            const int half = idx >> 8;              // 0 = K, 1 = V
            const int row  = (idx & 255) >> 2;
            const int seg  = (idx & 3) * 4;
            const uint32_t dst = (half ? sV : sK) + (uint32_t)buf * KV_TILE * 4
                               + (uint32_t)(row * QST + seg) * 4;
            cp_async16(dst, base + (size_t)(kt * 64 + row) * 384
                            + 128 + half * 128 + h * 16 + seg);
        }
    };

    // Q tile: 128 rows x 16 u32 = 512 float4; 256 thr x 2 iters
#pragma unroll
    for (int it = 0; it < 2; it++) {
        const int idx = tid + it * 256;
        const int row = idx >> 2, seg = (idx & 3) * 4;
        cp_async16(sQ + (uint32_t)(row * QST + seg) * 4,
                   base + (size_t)(q0 + row) * 384 + h * 16 + seg);
    }
    prefetch_kv(0, 0);
    cp_commit();
    cp_wait<0>();
    __syncthreads();

    uint32_t qa[2][4];
    {
        const int r0 = wid * 16;
#pragma unroll
        for (int kk = 0; kk < 2; kk++) {
            qa[kk][0] = Qp[(r0 + g)     * QST + kk * 8 + tg];
            qa[kk][1] = Qp[(r0 + g + 8) * QST + kk * 8 + tg];
            qa[kk][2] = Qp[(r0 + g)     * QST + kk * 8 + tg + 4];
            qa[kk][3] = Qp[(r0 + g + 8) * QST + kk * 8 + tg + 4];
        }
    }

    float o_[4][4];
#pragma unroll
    for (int nt = 0; nt < 4; nt++)
#pragma unroll
        for (int c = 0; c < 4; c++) o_[nt][c] = 0.f;
    float la0 = 0.f, la1 = 0.f, la2 = 0.f, la3 = 0.f;

    const int wrow = q0 + wid * 16;          // warp's first absolute q row
    const int nkt  = 2 * qt + 2;

    for (int kt = 0; kt < nkt; kt++) {
        if (kt > 0) { cp_wait<0>(); __syncthreads(); }
        if (kt + 1 < nkt) {
            prefetch_kv((kt + 1) & 1, kt + 1);
            cp_commit();
        }

        const int key0 = kt * 64;
        if (key0 > wrow + 15) continue;      // tile fully above this warp's diag

        const uint32_t kT = sK + (uint32_t)((kt & 1) * KV_TILE) * 4 + kfrag_base;
        const uint32_t vT = sV + (uint32_t)((kt & 1) * KV_TILE) * 4 + vfrag_base;

        // ---- S = Q K^T ----
        float s[8][4];
#pragma unroll
        for (int nt = 0; nt < 8; nt++)
#pragma unroll
            for (int c = 0; c < 4; c++) s[nt][c] = 0.f;

#pragma unroll
        for (int kk = 0; kk < 2; kk++) {
#pragma unroll
            for (int np = 0; np < 4; np++) {
                uint32_t b0, b1, b2, b3;
                ldm_x4(b0, b1, b2, b3,
                       kT + (uint32_t)(((np * 16) * QST + kk * 8) * 4));
                mma_f16(s[2 * np][0], s[2 * np][1], s[2 * np][2], s[2 * np][3],
                        qa[kk][0], qa[kk][1], qa[kk][2], qa[kk][3], b0, b1);
                mma_f16(s[2 * np + 1][0], s[2 * np + 1][1],
                        s[2 * np + 1][2], s[2 * np + 1][3],
                        qa[kk][0], qa[kk][1], qa[kk][2], qa[kk][3], b2, b3);
            }
        }

        // ---- causal mask (diagonal-straddling tiles; absolute indices) ----
        if (key0 + 63 > wrow) {
            const int ra = wrow + g;
#pragma unroll
            for (int nt = 0; nt < 8; nt++) {
                const int ca = key0 + nt * 8 + 2 * tg;
                if (ca     > ra)     s[nt][0] = -1e30f;
                if (ca + 1 > ra)     s[nt][1] = -1e30f;
                if (ca     > ra + 8) s[nt][2] = -1e30f;
                if (ca + 1 > ra + 8) s[nt][3] = -1e30f;
            }
        }

        // ---- P = exp2(S) straight into fp16 A-fragments ----
        uint32_t pa[4][4];
#pragma unroll
        for (int nt = 0; nt < 8; nt++) {
            pa[nt >> 1][(nt & 1) * 2]     = ex2_h2(pack_f16x2(s[nt][0], s[nt][1]));
            pa[nt >> 1][(nt & 1) * 2 + 1] = ex2_h2(pack_f16x2(s[nt][2], s[nt][3]));
        }

        // ---- l += P @ ones ----
#pragma unroll
        for (int kb = 0; kb < 4; kb++)
            mma_f16(la0, la1, la2, la3,
                    pa[kb][0], pa[kb][1], pa[kb][2], pa[kb][3], ONES_H2, ONES_H2);

        // ---- O += P V ----
#pragma unroll
        for (int kb = 0; kb < 4; kb++) {
#pragma unroll
            for (int np = 0; np < 2; np++) {
                uint32_t v0, v1, v2, v3;
                ldm_x4t(v0, v1, v2, v3,
                        vT + (uint32_t)(((kb * 16) * QST + np * 8) * 4));
                mma_f16(o_[2 * np][0], o_[2 * np][1], o_[2 * np][2], o_[2 * np][3],
                        pa[kb][0], pa[kb][1], pa[kb][2], pa[kb][3], v0, v1);
                mma_f16(o_[2 * np + 1][0], o_[2 * np + 1][1],
                        o_[2 * np + 1][2], o_[2 * np + 1][3],
                        pa[kb][0], pa[kb][1], pa[kb][2], pa[kb][3], v2, v3);
            }
        }
    }

    // ---- finalize: normalize, store fp16 ----
    const float i0 = 1.f / la0;
    const float i1 = 1.f / la2;
    uint32_t* yo  = yout + (size_t)(b * T_ + wrow + g) * 128 + h * 16;
    uint32_t* yo8 = yo + (size_t)8 * 128;
#pragma unroll
    for (int nt = 0; nt < 4; nt++) {
        yo [nt * 4 + tg] = pack_f16x2(o_[nt][0] * i0, o_[nt][1] * i0);
        yo8[nt * 4 + tg] = pack_f16x2(o_[nt][2] * i1, o_[nt][3] * i1);
    }
}

// ----------------------------------------------------------------------------
extern "C" void kernel_launch(void* const* d_in, const int* in_sizes, int n_in,
                              void* d_out, int out_size)
{
    const float* x      = (const float*)d_in[0];
    const float* w_qkv  = (const float*)d_in[1];
    const float* b_qkv  = (const float*)d_in[2];
    const float* w_proj = (const float*)d_in[3];
    const float* b_proj = (const float*)d_in[4];
    float* out = (float*)d_out;

    uint32_t *x16, *wqkv16, *wp16, *qkv16, *y16;
    cudaGetSymbolAddress((void**)&x16,    g_x16u);
    cudaGetSymbolAddress((void**)&wqkv16, g_wqkv16u);
    cudaGetSymbolAddress((void**)&wp16,   g_wp16u);
    cudaGetSymbolAddress((void**)&qkv16,  g_qkv16u);
    cudaGetSymbolAddress((void**)&y16,    g_y16u);

    const int M = B_ * T_;    // 8192
    const float qsc = 0.17677669529663687f * 1.4426950408889634f;

    cudaFuncSetAttribute(gemm16_kernel<1>,
                         cudaFuncAttributeMaxDynamicSharedMemorySize, GEMM_SMEM_BYTES);
    cudaFuncSetAttribute(gemm16_kernel<0>,
                         cudaFuncAttributeMaxDynamicSharedMemorySize, GEMM_SMEM_BYTES);
    cudaFuncSetAttribute(attn_kernel,
                         cudaFuncAttributeMaxDynamicSharedMemorySize, ATTN_SMEM_BYTES);

    // 0) pack inputs to fp16
    pack_f32_to_f16<<<(M * C_ / 4 + 255) / 256, 256>>>(x, x16, M * C_ / 4);
    pack_w_kpairs<<<(128 * (C3_ / 4) + 255) / 256, 256>>>(w_qkv, wqkv16, C_, C3_);
    pack_w_kpairs<<<(128 * (C_ / 4) + 255) / 256, 256>>>(w_proj, wp16, C_, C_);

    // 1) QKV GEMM (fp16 out, q pre-scaled)
    {
        dim3 grid(C3_ / 128, M / 128);
        gemm16_kernel<1><<<grid, 256, GEMM_SMEM_BYTES>>>(
            x16, wqkv16, b_qkv, qkv16, M, C3_, C_, qsc);
    }

    // 2) Causal attention (128 q-rows per block)
    {
        dim3 grid(T_ / 128, B_ * H_);
        attn_kernel<<<grid, 256, ATTN_SMEM_BYTES>>>(qkv16, y16);
    }

    // 3) Projection GEMM (fp32 out -> d_out)
    {
        dim3 grid(C_ / 128, M / 128);
        gemm16_kernel<0><<<grid, 256, GEMM_SMEM_BYTES>>>(
            y16, wp16, b_proj, out, M, C_, C_, 1.f);
    }
}

// round 15
// speedup vs baseline: 1.0906x; 1.0906x over previous
#include <cuda_runtime.h>
#include <cstdint>

#define B_   4
#define T_   2048
#define C_   256
#define H_   8
#define HD_  32
#define C3_  768

// ---- fp16 scratch (module-load allocated; legal under no-alloc rules) ------
__device__ uint32_t g_x16u  [8192 * 128];   // x packed fp16    [8192][256]
__device__ uint32_t g_wqkv16u[128 * 768];   // w_qkv k-pair-packed [128][768]
__device__ uint32_t g_wp16u [128 * 256];    // w_proj k-pair-packed [128][256]
__device__ uint32_t g_qkv16u[8192 * 384];   // qkv fp16 (q pre-scaled) [8192][768]
__device__ uint32_t g_y16u  [8192 * 128];   // attention out fp16 [8192][256]

// ---- helpers ---------------------------------------------------------------
__device__ __forceinline__ uint32_t pack_f16x2(float lo, float hi) {
    uint32_t r; asm("cvt.rn.f16x2.f32 %0, %1, %2;" : "=r"(r) : "f"(hi), "f"(lo));
    return r;
}
__device__ __forceinline__ uint32_t ex2_h2(uint32_t x) {
    uint32_t y; asm("ex2.approx.f16x2 %0, %1;" : "=r"(y) : "r"(x)); return y;
}
__device__ __forceinline__ void mma_f16(float& c0, float& c1, float& c2, float& c3,
                                        uint32_t a0, uint32_t a1, uint32_t a2, uint32_t a3,
                                        uint32_t b0, uint32_t b1) {
    asm volatile("mma.sync.aligned.m16n8k16.row.col.f32.f16.f16.f32 "
                 "{%0,%1,%2,%3}, {%4,%5,%6,%7}, {%8,%9}, {%0,%1,%2,%3};"
                 : "+f"(c0), "+f"(c1), "+f"(c2), "+f"(c3)
                 : "r"(a0), "r"(a1), "r"(a2), "r"(a3), "r"(b0), "r"(b1));
}
__device__ __forceinline__ void ldm_x4(uint32_t& r0, uint32_t& r1, uint32_t& r2,
                                       uint32_t& r3, uint32_t saddr) {
    asm volatile("ldmatrix.sync.aligned.m8n8.x4.shared.b16 {%0,%1,%2,%3}, [%4];"
                 : "=r"(r0), "=r"(r1), "=r"(r2), "=r"(r3) : "r"(saddr));
}
__device__ __forceinline__ void ldm_x4t(uint32_t& r0, uint32_t& r1, uint32_t& r2,
                                        uint32_t& r3, uint32_t saddr) {
    asm volatile("ldmatrix.sync.aligned.m8n8.x4.trans.shared.b16 {%0,%1,%2,%3}, [%4];"
                 : "=r"(r0), "=r"(r1), "=r"(r2), "=r"(r3) : "r"(saddr));
}
__device__ __forceinline__ void cp_async16(uint32_t saddr, const void* gptr) {
    asm volatile("cp.async.cg.shared.global [%0], [%1], 16;" :: "r"(saddr), "l"(gptr));
}
__device__ __forceinline__ void cp_commit() {
    asm volatile("cp.async.commit_group;");
}
template <int N>
__device__ __forceinline__ void cp_wait() {
    asm volatile("cp.async.wait_group %0;" :: "n"(N));
}

// ----------------------------------------------------------------------------
// Pack kernels
// ----------------------------------------------------------------------------
__global__ void pack_f32_to_f16(const float* __restrict__ in,
                                uint32_t* __restrict__ out, int n4)
{
    int i = blockIdx.x * blockDim.x + threadIdx.x;
    if (i < n4) {
        float4 v = ((const float4*)in)[i];
        uint2 o; o.x = pack_f16x2(v.x, v.y); o.y = pack_f16x2(v.z, v.w);
        ((uint2*)out)[i] = o;
    }
}

__global__ void pack_w_kpairs(const float* __restrict__ in,
                              uint32_t* __restrict__ out, int K, int N)
{
    int i = blockIdx.x * blockDim.x + threadIdx.x;
    int n4 = N >> 2;
    if (i < (K >> 1) * n4) {
        int kp = i / n4, c4 = (i - kp * n4) * 4;
        float4 a = *(const float4*)&in[(size_t)(2 * kp) * N + c4];
        float4 b = *(const float4*)&in[(size_t)(2 * kp + 1) * N + c4];
        uint4 o;
        o.x = pack_f16x2(a.x, b.x); o.y = pack_f16x2(a.y, b.y);
        o.z = pack_f16x2(a.z, b.z); o.w = pack_f16x2(a.w, b.w);
        *(uint4*)&out[(size_t)kp * N + c4] = o;
    }
}

// ----------------------------------------------------------------------------
// fp16 tensor-core GEMM, BK=32, 3-stage cp.async, A-frags via ldmatrix.x4.
// R15: BM=128, BN=64 (8 warps: 4m x 2n, 32x32 warp tile) — grid 2x larger,
// wave-quantization utilization 65% -> 86%.
// ----------------------------------------------------------------------------
#define AST 20
#define WST 72          // 72 % 32 == 8 -> B-frag banks (8tg+g)%32 conflict-free
#define GA_WORDS (128 * AST)
#define GW_WORDS (16 * WST)
#define GSTAGES 3
#define GEMM_SMEM_BYTES (GSTAGES * (GA_WORDS + GW_WORDS) * 4)

template <int MODE>
__global__ __launch_bounds__(256, 2)
void gemm16_kernel(const uint32_t* __restrict__ Apk,
                   const uint32_t* __restrict__ Wpk,
                   const float* __restrict__ bias,
                   void* __restrict__ outp,
                   int M, int N, int K, float qsc)
{
    extern __shared__ uint32_t gsm[];
    uint32_t* Asm = gsm;
    uint32_t* Wsm = gsm + GSTAGES * GA_WORDS;

    const int tid  = threadIdx.x;
    const int wid  = tid >> 5;
    const int lane = tid & 31;
    const int g    = lane >> 2;
    const int tg   = lane & 3;
    const int lm   = lane >> 3;
    const int lr   = lane & 7;
    const int wm   = wid & 3;       // 4 m-warps (32 rows each)
    const int wn   = wid >> 2;      // 2 n-warps (32 cols each)

    const int bm = blockIdx.y * 128;
    const int bn = blockIdx.x * 64;
    const int Kp2 = K >> 1;

    const int a_row = tid >> 1;          // 0..127
    const int a_seg = (tid & 1) * 8;     // kp offset {0,8}; +4 second cp
    const int w_row = tid >> 4;          // 0..15
    const int w_seg = (tid & 15) * 4;    // col offset (4 u32 = 16B)

    const uint32_t sA = (uint32_t)__cvta_generic_to_shared(Asm);
    const uint32_t sW = (uint32_t)__cvta_generic_to_shared(Wsm);

    const uint32_t afrag_base =
        (uint32_t)((((lm & 1) * 8 + lr) * AST + (lm >> 1) * 4) * 4);

    const int nChunks = K >> 5;          // 8

    auto prefetch = [&](int st, int c) {
        const uint32_t sa = sA + (uint32_t)st * GA_WORDS * 4;
        const uint32_t sw = sW + (uint32_t)st * GW_WORDS * 4;
        const int kp0 = c * 16;
        cp_async16(sa + (uint32_t)(a_row * AST + a_seg) * 4,
                   Apk + (size_t)(bm + a_row) * Kp2 + kp0 + a_seg);
        cp_async16(sa + (uint32_t)(a_row * AST + a_seg + 4) * 4,
                   Apk + (size_t)(bm + a_row) * Kp2 + kp0 + a_seg + 4);
        cp_async16(sw + (uint32_t)(w_row * WST + w_seg) * 4,
                   Wpk + (size_t)(kp0 + w_row) * N + bn + w_seg);
    };

    float acc[2][4][4];   // [m-tile r][n-tile c][reg]
#pragma unroll
    for (int r = 0; r < 2; r++)
#pragma unroll
        for (int c = 0; c < 4; c++)
#pragma unroll
            for (int i = 0; i < 4; i++) acc[r][c][i] = 0.f;

    prefetch(0, 0); cp_commit();
    prefetch(1, 1); cp_commit();

    for (int ch = 0; ch < nChunks; ch++) {
        if (ch + 1 < nChunks) cp_wait<1>(); else cp_wait<0>();
        __syncthreads();
        if (ch + 2 < nChunks) {
            prefetch((ch + 2) % GSTAGES, ch + 2);
            cp_commit();
        }

        const uint32_t Ab_s = sA + (uint32_t)((ch % GSTAGES) * GA_WORDS) * 4;
        const uint32_t* Wb = Wsm + (ch % GSTAGES) * GW_WORDS;

#pragma unroll
        for (int kk = 0; kk < 2; kk++) {
            uint32_t a[2][4];
#pragma unroll
            for (int r = 0; r < 2; r++) {
                ldm_x4(a[r][0], a[r][1], a[r][2], a[r][3],
                       Ab_s + afrag_base
                            + (uint32_t)(((wm * 32 + r * 16) * AST + kk * 8) * 4));
            }
            uint32_t bfr[4][2];
#pragma unroll
            for (int c = 0; c < 4; c++) {
                const int col = wn * 32 + c * 8 + g;
                bfr[c][0] = Wb[(kk * 8 + tg)     * WST + col];
                bfr[c][1] = Wb[(kk * 8 + tg + 4) * WST + col];
            }
#pragma unroll
            for (int r = 0; r < 2; r++)
#pragma unroll
                for (int c = 0; c < 4; c++)
                    mma_f16(acc[r][c][0], acc[r][c][1], acc[r][c][2], acc[r][c][3],
                            a[r][0], a[r][1], a[r][2], a[r][3], bfr[c][0], bfr[c][1]);
        }
    }

    // ---- epilogue ----
#pragma unroll
    for (int r = 0; r < 2; r++) {
        const int row0 = bm + wm * 32 + r * 16 + g;
#pragma unroll
        for (int c = 0; c < 4; c++) {
            const int col = bn + wn * 32 + c * 8 + 2 * tg;
            const float2 bb = *(const float2*)&bias[col];
            float v0 = acc[r][c][0] + bb.x, v1 = acc[r][c][1] + bb.y;
            float v2 = acc[r][c][2] + bb.x, v3 = acc[r][c][3] + bb.y;
            if (MODE == 1) {
                const float sc = (col < C_) ? qsc : 1.f;
                uint32_t* o16 = (uint32_t*)outp;
                o16[(size_t)row0       * (N >> 1) + (col >> 1)] = pack_f16x2(v0 * sc, v1 * sc);
                o16[(size_t)(row0 + 8) * (N >> 1) + (col >> 1)] = pack_f16x2(v2 * sc, v3 * sc);
            } else {
                float* o32 = (float*)outp;
                *(float2*)&o32[(size_t)row0 * N + col]       = make_float2(v0, v1);
                *(float2*)&o32[(size_t)(row0 + 8) * N + col] = make_float2(v2, v3);
            }
        }
    }
}

// ----------------------------------------------------------------------------
// Causal flash attention — R12 version verbatim (64 q-rows, 128 threads,
// all-fp16 mma, no-max softmax, ldmatrix K/V fragments). Known 50 us.
// ----------------------------------------------------------------------------
#define QST 20
#define ATT_TILE (64 * QST)
#define ATTN_SMEM_BYTES (5 * ATT_TILE * 4)
#define ONES_H2 0x3C003C00u

__global__ __launch_bounds__(128, 4)
void attn_kernel(const uint32_t* __restrict__ qkv, uint32_t* __restrict__ yout)
{
    extern __shared__ uint32_t sm[];
    uint32_t* Qp = sm;
    uint32_t* Kp = sm + ATT_TILE;
    uint32_t* Vp = Kp + 2 * ATT_TILE;

    const int tid  = threadIdx.x;
    const int wid  = tid >> 5;
    const int lane = tid & 31;
    const int g    = lane >> 2;
    const int tg   = lane & 3;
    const int lm   = lane >> 3;
    const int lr   = lane & 7;

    const int qt = gridDim.x - 1 - blockIdx.x;
    const int q0 = qt * 64;
    const int bh = blockIdx.y;
    const int b  = bh >> 3;
    const int h  = bh & 7;

    const uint32_t sQ = (uint32_t)__cvta_generic_to_shared(Qp);
    const uint32_t sK = (uint32_t)__cvta_generic_to_shared(Kp);
    const uint32_t sV = (uint32_t)__cvta_generic_to_shared(Vp);

    const uint32_t kfrag_base =
        (uint32_t)(((((lm >> 1) * 8) + lr) * QST + (lm & 1) * 4) * 4);
    const uint32_t vfrag_base =
        (uint32_t)(((((lm & 1) * 8) + lr) * QST + (lm >> 1) * 4) * 4);

    const uint32_t* base = qkv + (size_t)(b * T_) * 384;

    auto prefetch_kv = [&](int buf, int kt) {
#pragma unroll
        for (int it = 0; it < 4; it++) {
            const int idx  = tid + it * 128;
            const int half = idx >> 8;
            const int row  = (idx & 255) >> 2;
            const int seg  = (idx & 3) * 4;
            const uint32_t dst = (half ? sV : sK) + (uint32_t)buf * ATT_TILE * 4
                               + (uint32_t)(row * QST + seg) * 4;
            cp_async16(dst, base + (size_t)(kt * 64 + row) * 384
                            + 128 + half * 128 + h * 16 + seg);
        }
    };

#pragma unroll
    for (int it = 0; it < 2; it++) {
        const int idx = tid + it * 128;
        const int row = idx >> 2, seg = (idx & 3) * 4;
        cp_async16(sQ + (uint32_t)(row * QST + seg) * 4,
                   base + (size_t)(q0 + row) * 384 + h * 16 + seg);
    }
    prefetch_kv(0, 0);
    cp_commit();
    cp_wait<0>();
    __syncthreads();

    uint32_t qa[2][4];
    {
        const int r0 = wid * 16;
#pragma unroll
        for (int kk = 0; kk < 2; kk++) {
            qa[kk][0] = Qp[(r0 + g)     * QST + kk * 8 + tg];
            qa[kk][1] = Qp[(r0 + g + 8) * QST + kk * 8 + tg];
            qa[kk][2] = Qp[(r0 + g)     * QST + kk * 8 + tg + 4];
            qa[kk][3] = Qp[(r0 + g + 8) * QST + kk * 8 + tg + 4];
        }
    }

    float o_[4][4];
#pragma unroll
    for (int nt = 0; nt < 4; nt++)
#pragma unroll
        for (int c = 0; c < 4; c++) o_[nt][c] = 0.f;
    float la0 = 0.f, la1 = 0.f, la2 = 0.f, la3 = 0.f;

    const int nkt = qt + 1;
    for (int kt = 0; kt < nkt; kt++) {
        if (kt > 0) { cp_wait<0>(); __syncthreads(); }
        if (kt + 1 < nkt) {
            prefetch_kv((kt + 1) & 1, kt + 1);
            cp_commit();
        }

        const uint32_t kT = sK + (uint32_t)((kt & 1) * ATT_TILE) * 4 + kfrag_base;
        const uint32_t vT = sV + (uint32_t)((kt & 1) * ATT_TILE) * 4 + vfrag_base;

        float s[8][4];
#pragma unroll
        for (int nt = 0; nt < 8; nt++)
#pragma unroll
            for (int c = 0; c < 4; c++) s[nt][c] = 0.f;

#pragma unroll
        for (int kk = 0; kk < 2; kk++) {
#pragma unroll
            for (int np = 0; np < 4; np++) {
                uint32_t b0, b1, b2, b3;
                ldm_x4(b0, b1, b2, b3,
                       kT + (uint32_t)(((np * 16) * QST + kk * 8) * 4));
                mma_f16(s[2 * np][0], s[2 * np][1], s[2 * np][2], s[2 * np][3],
                        qa[kk][0], qa[kk][1], qa[kk][2], qa[kk][3], b0, b1);
                mma_f16(s[2 * np + 1][0], s[2 * np + 1][1],
                        s[2 * np + 1][2], s[2 * np + 1][3],
                        qa[kk][0], qa[kk][1], qa[kk][2], qa[kk][3], b2, b3);
            }
        }

        if (kt == nkt - 1) {
            const int r0 = wid * 16 + g;
#pragma unroll
            for (int nt = 0; nt < 8; nt++) {
                const int col0 = nt * 8 + 2 * tg;
                if (col0     > r0)     s[nt][0] = -1e30f;
                if (col0 + 1 > r0)     s[nt][1] = -1e30f;
                if (col0     > r0 + 8) s[nt][2] = -1e30f;
                if (col0 + 1 > r0 + 8) s[nt][3] = -1e30f;
            }
        }

        uint32_t pa[4][4];
#pragma unroll
        for (int nt = 0; nt < 8; nt++) {
            pa[nt >> 1][(nt & 1) * 2]     = ex2_h2(pack_f16x2(s[nt][0], s[nt][1]));
            pa[nt >> 1][(nt & 1) * 2 + 1] = ex2_h2(pack_f16x2(s[nt][2], s[nt][3]));
        }

#pragma unroll
        for (int kb = 0; kb < 4; kb++)
            mma_f16(la0, la1, la2, la3,
                    pa[kb][0], pa[kb][1], pa[kb][2], pa[kb][3], ONES_H2, ONES_H2);

#pragma unroll
        for (int kb = 0; kb < 4; kb++) {
#pragma unroll
            for (int np = 0; np < 2; np++) {
                uint32_t v0, v1, v2, v3;
                ldm_x4t(v0, v1, v2, v3,
                        vT + (uint32_t)(((kb * 16) * QST + np * 8) * 4));
                mma_f16(o_[2 * np][0], o_[2 * np][1], o_[2 * np][2], o_[2 * np][3],
                        pa[kb][0], pa[kb][1], pa[kb][2], pa[kb][3], v0, v1);
                mma_f16(o_[2 * np + 1][0], o_[2 * np + 1][1],
                        o_[2 * np + 1][2], o_[2 * np + 1][3],
                        pa[kb][0], pa[kb][1], pa[kb][2], pa[kb][3], v2, v3);
            }
        }
    }

    const float i0 = 1.f / la0;
    const float i1 = 1.f / la2;
    uint32_t* yo  = yout + (size_t)(b * T_ + q0 + wid * 16 + g) * 128 + h * 16;
    uint32_t* yo8 = yo + (size_t)8 * 128;
#pragma unroll
    for (int nt = 0; nt < 4; nt++) {
        yo [nt * 4 + tg] = pack_f16x2(o_[nt][0] * i0, o_[nt][1] * i0);
        yo8[nt * 4 + tg] = pack_f16x2(o_[nt][2] * i1, o_[nt][3] * i1);
    }
}

// ----------------------------------------------------------------------------
extern "C" void kernel_launch(void* const* d_in, const int* in_sizes, int n_in,
                              void* d_out, int out_size)
{
    const float* x      = (const float*)d_in[0];
    const float* w_qkv  = (const float*)d_in[1];
    const float* b_qkv  = (const float*)d_in[2];
    const float* w_proj = (const float*)d_in[3];
    const float* b_proj = (const float*)d_in[4];
    float* out = (float*)d_out;

    uint32_t *x16, *wqkv16, *wp16, *qkv16, *y16;
    cudaGetSymbolAddress((void**)&x16,    g_x16u);
    cudaGetSymbolAddress((void**)&wqkv16, g_wqkv16u);
    cudaGetSymbolAddress((void**)&wp16,   g_wp16u);
    cudaGetSymbolAddress((void**)&qkv16,  g_qkv16u);
    cudaGetSymbolAddress((void**)&y16,    g_y16u);

    const int M = B_ * T_;    // 8192
    const float qsc = 0.17677669529663687f * 1.4426950408889634f;

    cudaFuncSetAttribute(gemm16_kernel<1>,
                         cudaFuncAttributeMaxDynamicSharedMemorySize, GEMM_SMEM_BYTES);
    cudaFuncSetAttribute(gemm16_kernel<0>,
                         cudaFuncAttributeMaxDynamicSharedMemorySize, GEMM_SMEM_BYTES);
    cudaFuncSetAttribute(attn_kernel,
                         cudaFuncAttributeMaxDynamicSharedMemorySize, ATTN_SMEM_BYTES);

    // 0) pack inputs to fp16
    pack_f32_to_f16<<<(M * C_ / 4 + 255) / 256, 256>>>(x, x16, M * C_ / 4);
    pack_w_kpairs<<<(128 * (C3_ / 4) + 255) / 256, 256>>>(w_qkv, wqkv16, C_, C3_);
    pack_w_kpairs<<<(128 * (C_ / 4) + 255) / 256, 256>>>(w_proj, wp16, C_, C_);

    // 1) QKV GEMM (fp16 out, q pre-scaled)  — grid 768, util 86%
    {
        dim3 grid(C3_ / 64, M / 128);
        gemm16_kernel<1><<<grid, 256, GEMM_SMEM_BYTES>>>(
            x16, wqkv16, b_qkv, qkv16, M, C3_, C_, qsc);
    }

    // 2) Causal attention (R12 config)
    {
        dim3 grid(T_ / 64, B_ * H_);
        attn_kernel<<<grid, 128, ATTN_SMEM_BYTES>>>(qkv16, y16);
    }

    // 3) Projection GEMM (fp32 out -> d_out) — grid 256, single wave
    {
        dim3 grid(C_ / 64, M / 128);
        gemm16_kernel<0><<<grid, 256, GEMM_SMEM_BYTES>>>(
            y16, wp16, b_proj, out, M, C_, C_, 1.f);
    }
}

// round 16
// speedup vs baseline: 1.1641x; 1.0675x over previous
#include <cuda_runtime.h>
#include <cstdint>

#define B_   4
#define T_   2048
#define C_   256
#define H_   8
#define HD_  32
#define C3_  768

// ---- fp16 scratch (module-load allocated; legal under no-alloc rules) ------
__device__ uint32_t g_x16u  [8192 * 128];   // x packed fp16    [8192][256]
__device__ uint32_t g_wqkv16u[128 * 768];   // w_qkv k-pair-packed [128][768]
__device__ uint32_t g_wp16u [128 * 256];    // w_proj k-pair-packed [128][256]
__device__ uint32_t g_qkv16u[8192 * 384];   // qkv fp16 (q pre-scaled) [8192][768]
__device__ uint32_t g_y16u  [8192 * 128];   // attention out fp16 [8192][256]
__device__ uint32_t g_ctr[2];               // persistent-GEMM work queues

// ---- helpers ---------------------------------------------------------------
__device__ __forceinline__ uint32_t pack_f16x2(float lo, float hi) {
    uint32_t r; asm("cvt.rn.f16x2.f32 %0, %1, %2;" : "=r"(r) : "f"(hi), "f"(lo));
    return r;
}
__device__ __forceinline__ uint32_t ex2_h2(uint32_t x) {
    uint32_t y; asm("ex2.approx.f16x2 %0, %1;" : "=r"(y) : "r"(x)); return y;
}
__device__ __forceinline__ void mma_f16(float& c0, float& c1, float& c2, float& c3,
                                        uint32_t a0, uint32_t a1, uint32_t a2, uint32_t a3,
                                        uint32_t b0, uint32_t b1) {
    asm volatile("mma.sync.aligned.m16n8k16.row.col.f32.f16.f16.f32 "
                 "{%0,%1,%2,%3}, {%4,%5,%6,%7}, {%8,%9}, {%0,%1,%2,%3};"
                 : "+f"(c0), "+f"(c1), "+f"(c2), "+f"(c3)
                 : "r"(a0), "r"(a1), "r"(a2), "r"(a3), "r"(b0), "r"(b1));
}
__device__ __forceinline__ void ldm_x4(uint32_t& r0, uint32_t& r1, uint32_t& r2,
                                       uint32_t& r3, uint32_t saddr) {
    asm volatile("ldmatrix.sync.aligned.m8n8.x4.shared.b16 {%0,%1,%2,%3}, [%4];"
                 : "=r"(r0), "=r"(r1), "=r"(r2), "=r"(r3) : "r"(saddr));
}
__device__ __forceinline__ void ldm_x4t(uint32_t& r0, uint32_t& r1, uint32_t& r2,
                                        uint32_t& r3, uint32_t saddr) {
    asm volatile("ldmatrix.sync.aligned.m8n8.x4.trans.shared.b16 {%0,%1,%2,%3}, [%4];"
                 : "=r"(r0), "=r"(r1), "=r"(r2), "=r"(r3) : "r"(saddr));
}
__device__ __forceinline__ void cp_async16(uint32_t saddr, const void* gptr) {
    asm volatile("cp.async.cg.shared.global [%0], [%1], 16;" :: "r"(saddr), "l"(gptr));
}
__device__ __forceinline__ void cp_commit() {
    asm volatile("cp.async.commit_group;");
}
template <int N>
__device__ __forceinline__ void cp_wait() {
    asm volatile("cp.async.wait_group %0;" :: "n"(N));
}

// ----------------------------------------------------------------------------
// Merged pack kernel: x -> fp16, both weights -> k-pair-packed fp16,
// and resets the persistent-GEMM work-queue counters (runs first each launch).
// ----------------------------------------------------------------------------
#define PK_X   (8192 * 256 / 4)             // 524288 float4 of x
#define PK_WQ  (128 * (C3_ / 4))            // 24576 quads of w_qkv
#define PK_WP  (128 * (C_ / 4))             // 8192 quads of w_proj
#define PK_TOT (PK_X + PK_WQ + PK_WP)

__global__ void pack_all(const float* __restrict__ x,
                         const float* __restrict__ wq,
                         const float* __restrict__ wp,
                         uint32_t* __restrict__ x16,
                         uint32_t* __restrict__ wq16,
                         uint32_t* __restrict__ wp16)
{
    int i = blockIdx.x * blockDim.x + threadIdx.x;
    if (i == 0) { g_ctr[0] = 0; g_ctr[1] = 0; }
    if (i < PK_X) {
        float4 v = ((const float4*)x)[i];
        uint2 o; o.x = pack_f16x2(v.x, v.y); o.y = pack_f16x2(v.z, v.w);
        ((uint2*)x16)[i] = o;
    } else if (i < PK_X + PK_WQ) {
        int j = i - PK_X;
        int n4 = C3_ >> 2;
        int kp = j / n4, c4 = (j - kp * n4) * 4;
        float4 a = *(const float4*)&wq[(size_t)(2 * kp) * C3_ + c4];
        float4 b = *(const float4*)&wq[(size_t)(2 * kp + 1) * C3_ + c4];
        uint4 o;
        o.x = pack_f16x2(a.x, b.x); o.y = pack_f16x2(a.y, b.y);
        o.z = pack_f16x2(a.z, b.z); o.w = pack_f16x2(a.w, b.w);
        *(uint4*)&wq16[(size_t)kp * C3_ + c4] = o;
    } else if (i < PK_TOT) {
        int j = i - PK_X - PK_WQ;
        int n4 = C_ >> 2;
        int kp = j / n4, c4 = (j - kp * n4) * 4;
        float4 a = *(const float4*)&wp[(size_t)(2 * kp) * C_ + c4];
        float4 b = *(const float4*)&wp[(size_t)(2 * kp + 1) * C_ + c4];
        uint4 o;
        o.x = pack_f16x2(a.x, b.x); o.y = pack_f16x2(a.y, b.y);
        o.z = pack_f16x2(a.z, b.z); o.w = pack_f16x2(a.w, b.w);
        *(uint4*)&wp16[(size_t)kp * C_ + c4] = o;
    }
}

// ----------------------------------------------------------------------------
// fp16 tensor-core GEMM, R12 tile config (BM=128, BN=128, BK=32, 3-stage
// cp.async, ldmatrix A-frags), made PERSISTENT: blocks pull 128x128 tiles
// from an atomic queue -> work-stealing balance across SMs. Tile->output
// mapping is fixed, so results are bit-identical to the static grid.
// ----------------------------------------------------------------------------
#define AST 20
#define WST 136
#define GA_WORDS (128 * AST)
#define GW_WORDS (16 * WST)
#define GSTAGES 3
#define GEMM_SMEM_BYTES (GSTAGES * (GA_WORDS + GW_WORDS) * 4)

template <int MODE>
__global__ __launch_bounds__(256, 2)
void gemm16_kernel(const uint32_t* __restrict__ Apk,
                   const uint32_t* __restrict__ Wpk,
                   const float* __restrict__ bias,
                   void* __restrict__ outp,
                   int M, int N, int K, float qsc, int ctr_idx, int nTiles)
{
    extern __shared__ uint32_t gsm[];
    uint32_t* Asm = gsm;
    uint32_t* Wsm = gsm + GSTAGES * GA_WORDS;
    __shared__ uint32_t s_tile;

    const int tid  = threadIdx.x;
    const int wid  = tid >> 5;
    const int lane = tid & 31;
    const int g    = lane >> 2;
    const int tg   = lane & 3;
    const int lm   = lane >> 3;
    const int lr   = lane & 7;
    const int wm   = wid & 1;
    const int wn   = wid >> 1;

    const int Kp2 = K >> 1;
    const int nTilesX = N >> 7;          // N/128

    const int a_row = tid >> 1;
    const int a_seg = (tid & 1) * 8;
    const int w_row = tid >> 4;
    const int w_seg = (tid & 15) * 8;

    const uint32_t sA = (uint32_t)__cvta_generic_to_shared(Asm);
    const uint32_t sW = (uint32_t)__cvta_generic_to_shared(Wsm);

    const uint32_t afrag_base =
        (uint32_t)((((lm & 1) * 8 + lr) * AST + (lm >> 1) * 4) * 4);

    const int nChunks = K >> 5;          // 8

    for (;;) {
        __syncthreads();                 // all threads done with previous s_tile
        if (tid == 0) s_tile = atomicAdd(&g_ctr[ctr_idx], 1u);
        __syncthreads();
        const int t = (int)s_tile;
        if (t >= nTiles) break;

        const int bm = (t / nTilesX) * 128;
        const int bn = (t % nTilesX) * 128;

        auto prefetch = [&](int st, int c) {
            const uint32_t sa = sA + (uint32_t)st * GA_WORDS * 4;
            const uint32_t sw = sW + (uint32_t)st * GW_WORDS * 4;
            const int kp0 = c * 16;
            cp_async16(sa + (uint32_t)(a_row * AST + a_seg) * 4,
                       Apk + (size_t)(bm + a_row) * Kp2 + kp0 + a_seg);
            cp_async16(sa + (uint32_t)(a_row * AST + a_seg + 4) * 4,
                       Apk + (size_t)(bm + a_row) * Kp2 + kp0 + a_seg + 4);
            cp_async16(sw + (uint32_t)(w_row * WST + w_seg) * 4,
                       Wpk + (size_t)(kp0 + w_row) * N + bn + w_seg);
            cp_async16(sw + (uint32_t)(w_row * WST + w_seg + 4) * 4,
                       Wpk + (size_t)(kp0 + w_row) * N + bn + w_seg + 4);
        };

        float acc[4][4][4];
#pragma unroll
        for (int r = 0; r < 4; r++)
#pragma unroll
            for (int c = 0; c < 4; c++)
#pragma unroll
                for (int i = 0; i < 4; i++) acc[r][c][i] = 0.f;

        prefetch(0, 0); cp_commit();
        prefetch(1, 1); cp_commit();

        for (int ch = 0; ch < nChunks; ch++) {
            if (ch + 1 < nChunks) cp_wait<1>(); else cp_wait<0>();
            __syncthreads();
            if (ch + 2 < nChunks) {
                prefetch((ch + 2) % GSTAGES, ch + 2);
                cp_commit();
            }

            const uint32_t Ab_s = sA + (uint32_t)((ch % GSTAGES) * GA_WORDS) * 4;
            const uint32_t* Wb = Wsm + (ch % GSTAGES) * GW_WORDS;

#pragma unroll
            for (int kk = 0; kk < 2; kk++) {
                uint32_t a[4][4];
#pragma unroll
                for (int r = 0; r < 4; r++) {
                    ldm_x4(a[r][0], a[r][1], a[r][2], a[r][3],
                           Ab_s + afrag_base
                                + (uint32_t)(((wm * 64 + r * 16) * AST + kk * 8) * 4));
                }
                uint32_t bfr[4][2];
#pragma unroll
                for (int c = 0; c < 4; c++) {
                    const int col = wn * 32 + c * 8 + g;
                    bfr[c][0] = Wb[(kk * 8 + tg)     * WST + col];
                    bfr[c][1] = Wb[(kk * 8 + tg + 4) * WST + col];
                }
#pragma unroll
                for (int r = 0; r < 4; r++)
#pragma unroll
                    for (int c = 0; c < 4; c++)
                        mma_f16(acc[r][c][0], acc[r][c][1], acc[r][c][2], acc[r][c][3],
                                a[r][0], a[r][1], a[r][2], a[r][3], bfr[c][0], bfr[c][1]);
            }
            __syncthreads();   // smem stage reuse safe before next tile/chunk
        }

        // ---- epilogue ----
#pragma unroll
        for (int r = 0; r < 4; r++) {
            const int row0 = bm + wm * 64 + r * 16 + g;
#pragma unroll
            for (int c = 0; c < 4; c++) {
                const int col = bn + wn * 32 + c * 8 + 2 * tg;
                const float2 bb = *(const float2*)&bias[col];
                float v0 = acc[r][c][0] + bb.x, v1 = acc[r][c][1] + bb.y;
                float v2 = acc[r][c][2] + bb.x, v3 = acc[r][c][3] + bb.y;
                if (MODE == 1) {
                    const float sc = (col < C_) ? qsc : 1.f;
                    uint32_t* o16 = (uint32_t*)outp;
                    o16[(size_t)row0       * (N >> 1) + (col >> 1)] = pack_f16x2(v0 * sc, v1 * sc);
                    o16[(size_t)(row0 + 8) * (N >> 1) + (col >> 1)] = pack_f16x2(v2 * sc, v3 * sc);
                } else {
                    float* o32 = (float*)outp;
                    *(float2*)&o32[(size_t)row0 * N + col]       = make_float2(v0, v1);
                    *(float2*)&o32[(size_t)(row0 + 8) * N + col] = make_float2(v2, v3);
                }
            }
        }
    }
}

// ----------------------------------------------------------------------------
// Causal flash attention — R12 version verbatim (64 q-rows, 128 threads,
// all-fp16 mma, no-max softmax, ldmatrix K/V fragments).
// ----------------------------------------------------------------------------
#define QST 20
#define ATT_TILE (64 * QST)
#define ATTN_SMEM_BYTES (5 * ATT_TILE * 4)
#define ONES_H2 0x3C003C00u

__global__ __launch_bounds__(128, 4)
void attn_kernel(const uint32_t* __restrict__ qkv, uint32_t* __restrict__ yout)
{
    extern __shared__ uint32_t sm[];
    uint32_t* Qp = sm;
    uint32_t* Kp = sm + ATT_TILE;
    uint32_t* Vp = Kp + 2 * ATT_TILE;

    const int tid  = threadIdx.x;
    const int wid  = tid >> 5;
    const int lane = tid & 31;
    const int g    = lane >> 2;
    const int tg   = lane & 3;
    const int lm   = lane >> 3;
    const int lr   = lane & 7;

    const int qt = gridDim.x - 1 - blockIdx.x;
    const int q0 = qt * 64;
    const int bh = blockIdx.y;
    const int b  = bh >> 3;
    const int h  = bh & 7;

    const uint32_t sQ = (uint32_t)__cvta_generic_to_shared(Qp);
    const uint32_t sK = (uint32_t)__cvta_generic_to_shared(Kp);
    const uint32_t sV = (uint32_t)__cvta_generic_to_shared(Vp);

    const uint32_t kfrag_base =
        (uint32_t)(((((lm >> 1) * 8) + lr) * QST + (lm & 1) * 4) * 4);
    const uint32_t vfrag_base =
        (uint32_t)(((((lm & 1) * 8) + lr) * QST + (lm >> 1) * 4) * 4);

    const uint32_t* base = qkv + (size_t)(b * T_) * 384;

    auto prefetch_kv = [&](int buf, int kt) {
#pragma unroll
        for (int it = 0; it < 4; it++) {
            const int idx  = tid + it * 128;
            const int half = idx >> 8;
            const int row  = (idx & 255) >> 2;
            const int seg  = (idx & 3) * 4;
            const uint32_t dst = (half ? sV : sK) + (uint32_t)buf * ATT_TILE * 4
                               + (uint32_t)(row * QST + seg) * 4;
            cp_async16(dst, base + (size_t)(kt * 64 + row) * 384
                            + 128 + half * 128 + h * 16 + seg);
        }
    };

#pragma unroll
    for (int it = 0; it < 2; it++) {
        const int idx = tid + it * 128;
        const int row = idx >> 2, seg = (idx & 3) * 4;
        cp_async16(sQ + (uint32_t)(row * QST + seg) * 4,
                   base + (size_t)(q0 + row) * 384 + h * 16 + seg);
    }
    prefetch_kv(0, 0);
    cp_commit();
    cp_wait<0>();
    __syncthreads();

    uint32_t qa[2][4];
    {
        const int r0 = wid * 16;
#pragma unroll
        for (int kk = 0; kk < 2; kk++) {
            qa[kk][0] = Qp[(r0 + g)     * QST + kk * 8 + tg];
            qa[kk][1] = Qp[(r0 + g + 8) * QST + kk * 8 + tg];
            qa[kk][2] = Qp[(r0 + g)     * QST + kk * 8 + tg + 4];
            qa[kk][3] = Qp[(r0 + g + 8) * QST + kk * 8 + tg + 4];
        }
    }

    float o_[4][4];
#pragma unroll
    for (int nt = 0; nt < 4; nt++)
#pragma unroll
        for (int c = 0; c < 4; c++) o_[nt][c] = 0.f;
    float la0 = 0.f, la1 = 0.f, la2 = 0.f, la3 = 0.f;

    const int nkt = qt + 1;
    for (int kt = 0; kt < nkt; kt++) {
        if (kt > 0) { cp_wait<0>(); __syncthreads(); }
        if (kt + 1 < nkt) {
            prefetch_kv((kt + 1) & 1, kt + 1);
            cp_commit();
        }

        const uint32_t kT = sK + (uint32_t)((kt & 1) * ATT_TILE) * 4 + kfrag_base;
        const uint32_t vT = sV + (uint32_t)((kt & 1) * ATT_TILE) * 4 + vfrag_base;

        float s[8][4];
#pragma unroll
        for (int nt = 0; nt < 8; nt++)
#pragma unroll
            for (int c = 0; c < 4; c++) s[nt][c] = 0.f;

#pragma unroll
        for (int kk = 0; kk < 2; kk++) {
#pragma unroll
            for (int np = 0; np < 4; np++) {
                uint32_t b0, b1, b2, b3;
                ldm_x4(b0, b1, b2, b3,
                       kT + (uint32_t)(((np * 16) * QST + kk * 8) * 4));
                mma_f16(s[2 * np][0], s[2 * np][1], s[2 * np][2], s[2 * np][3],
                        qa[kk][0], qa[kk][1], qa[kk][2], qa[kk][3], b0, b1);
                mma_f16(s[2 * np + 1][0], s[2 * np + 1][1],
                        s[2 * np + 1][2], s[2 * np + 1][3],
                        qa[kk][0], qa[kk][1], qa[kk][2], qa[kk][3], b2, b3);
            }
        }

        if (kt == nkt - 1) {
            const int r0 = wid * 16 + g;
#pragma unroll
            for (int nt = 0; nt < 8; nt++) {
                const int col0 = nt * 8 + 2 * tg;
                if (col0     > r0)     s[nt][0] = -1e30f;
                if (col0 + 1 > r0)     s[nt][1] = -1e30f;
                if (col0     > r0 + 8) s[nt][2] = -1e30f;
                if (col0 + 1 > r0 + 8) s[nt][3] = -1e30f;
            }
        }

        uint32_t pa[4][4];
#pragma unroll
        for (int nt = 0; nt < 8; nt++) {
            pa[nt >> 1][(nt & 1) * 2]     = ex2_h2(pack_f16x2(s[nt][0], s[nt][1]));
            pa[nt >> 1][(nt & 1) * 2 + 1] = ex2_h2(pack_f16x2(s[nt][2], s[nt][3]));
        }

#pragma unroll
        for (int kb = 0; kb < 4; kb++)
            mma_f16(la0, la1, la2, la3,
                    pa[kb][0], pa[kb][1], pa[kb][2], pa[kb][3], ONES_H2, ONES_H2);

#pragma unroll
        for (int kb = 0; kb < 4; kb++) {
#pragma unroll
            for (int np = 0; np < 2; np++) {
                uint32_t v0, v1, v2, v3;
                ldm_x4t(v0, v1, v2, v3,
                        vT + (uint32_t)(((kb * 16) * QST + np * 8) * 4));
                mma_f16(o_[2 * np][0], o_[2 * np][1], o_[2 * np][2], o_[2 * np][3],
                        pa[kb][0], pa[kb][1], pa[kb][2], pa[kb][3], v0, v1);
                mma_f16(o_[2 * np + 1][0], o_[2 * np + 1][1],
                        o_[2 * np + 1][2], o_[2 * np + 1][3],
                        pa[kb][0], pa[kb][1], pa[kb][2], pa[kb][3], v2, v3);
            }
        }
    }

    const float i0 = 1.f / la0;
    const float i1 = 1.f / la2;
    uint32_t* yo  = yout + (size_t)(b * T_ + q0 + wid * 16 + g) * 128 + h * 16;
    uint32_t* yo8 = yo + (size_t)8 * 128;
#pragma unroll
    for (int nt = 0; nt < 4; nt++) {
        yo [nt * 4 + tg] = pack_f16x2(o_[nt][0] * i0, o_[nt][1] * i0);
        yo8[nt * 4 + tg] = pack_f16x2(o_[nt][2] * i1, o_[nt][3] * i1);
    }
}

// ----------------------------------------------------------------------------
extern "C" void kernel_launch(void* const* d_in, const int* in_sizes, int n_in,
                              void* d_out, int out_size)
{
    const float* x      = (const float*)d_in[0];
    const float* w_qkv  = (const float*)d_in[1];
    const float* b_qkv  = (const float*)d_in[2];
    const float* w_proj = (const float*)d_in[3];
    const float* b_proj = (const float*)d_in[4];
    float* out = (float*)d_out;

    uint32_t *x16, *wqkv16, *wp16, *qkv16, *y16;
    cudaGetSymbolAddress((void**)&x16,    g_x16u);
    cudaGetSymbolAddress((void**)&wqkv16, g_wqkv16u);
    cudaGetSymbolAddress((void**)&wp16,   g_wp16u);
    cudaGetSymbolAddress((void**)&qkv16,  g_qkv16u);
    cudaGetSymbolAddress((void**)&y16,    g_y16u);

    const int M = B_ * T_;    // 8192
    const float qsc = 0.17677669529663687f * 1.4426950408889634f;

    cudaFuncSetAttribute(gemm16_kernel<1>,
                         cudaFuncAttributeMaxDynamicSharedMemorySize, GEMM_SMEM_BYTES);
    cudaFuncSetAttribute(gemm16_kernel<0>,
                         cudaFuncAttributeMaxDynamicSharedMemorySize, GEMM_SMEM_BYTES);
    cudaFuncSetAttribute(attn_kernel,
                         cudaFuncAttributeMaxDynamicSharedMemorySize, ATTN_SMEM_BYTES);

    // 0) merged pack + work-queue reset
    pack_all<<<(PK_TOT + 255) / 256, 256>>>(x, w_qkv, w_proj, x16, wqkv16, wp16);

    // 1) QKV GEMM (persistent; 384 tiles of 128x128, queue 0)
    {
        const int nTiles = (M / 128) * (C3_ / 128);      // 384
        gemm16_kernel<1><<<296, 256, GEMM_SMEM_BYTES>>>(
            x16, wqkv16, b_qkv, qkv16, M, C3_, C_, qsc, 0, nTiles);
    }

    // 2) Causal attention (R12 config)
    {
        dim3 grid(T_ / 64, B_ * H_);
        attn_kernel<<<grid, 128, ATTN_SMEM_BYTES>>>(qkv16, y16);
    }

    // 3) Projection GEMM (persistent; 128 tiles, queue 1) -> d_out
    {
        const int nTiles = (M / 128) * (C_ / 128);       // 128
        gemm16_kernel<0><<<128, 256, GEMM_SMEM_BYTES>>>(
            y16, wp16, b_proj, out, M, C_, C_, 1.f, 1, nTiles);
    }
}

// round 17
// speedup vs baseline: 1.1681x; 1.0034x over previous
#include <cuda_runtime.h>
#include <cstdint>

#define B_   4
#define T_   2048
#define C_   256
#define H_   8
#define HD_  32
#define C3_  768

// ---- fp16 scratch (module-load allocated; legal under no-alloc rules) ------
__device__ uint32_t g_x16u  [8192 * 128];   // x packed fp16    [8192][256]
__device__ uint32_t g_wqkv16u[128 * 768];   // w_qkv k-pair-packed [128][768]
__device__ uint32_t g_wp16u [128 * 256];    // w_proj k-pair-packed [128][256]
__device__ uint32_t g_qkv16u[8192 * 384];   // qkv fp16 (q pre-scaled) [8192][768]
__device__ uint32_t g_y16u  [8192 * 128];   // attention out fp16 [8192][256]
__device__ uint32_t g_ctr[2];               // persistent-GEMM work queues

// ---- helpers ---------------------------------------------------------------
__device__ __forceinline__ uint32_t pack_f16x2(float lo, float hi) {
    uint32_t r; asm("cvt.rn.f16x2.f32 %0, %1, %2;" : "=r"(r) : "f"(hi), "f"(lo));
    return r;
}
__device__ __forceinline__ uint32_t ex2_h2(uint32_t x) {
    uint32_t y; asm("ex2.approx.f16x2 %0, %1;" : "=r"(y) : "r"(x)); return y;
}
__device__ __forceinline__ void mma_f16(float& c0, float& c1, float& c2, float& c3,
                                        uint32_t a0, uint32_t a1, uint32_t a2, uint32_t a3,
                                        uint32_t b0, uint32_t b1) {
    asm volatile("mma.sync.aligned.m16n8k16.row.col.f32.f16.f16.f32 "
                 "{%0,%1,%2,%3}, {%4,%5,%6,%7}, {%8,%9}, {%0,%1,%2,%3};"
                 : "+f"(c0), "+f"(c1), "+f"(c2), "+f"(c3)
                 : "r"(a0), "r"(a1), "r"(a2), "r"(a3), "r"(b0), "r"(b1));
}
__device__ __forceinline__ void ldm_x4(uint32_t& r0, uint32_t& r1, uint32_t& r2,
                                       uint32_t& r3, uint32_t saddr) {
    asm volatile("ldmatrix.sync.aligned.m8n8.x4.shared.b16 {%0,%1,%2,%3}, [%4];"
                 : "=r"(r0), "=r"(r1), "=r"(r2), "=r"(r3) : "r"(saddr));
}
__device__ __forceinline__ void ldm_x4t(uint32_t& r0, uint32_t& r1, uint32_t& r2,
                                        uint32_t& r3, uint32_t saddr) {
    asm volatile("ldmatrix.sync.aligned.m8n8.x4.trans.shared.b16 {%0,%1,%2,%3}, [%4];"
                 : "=r"(r0), "=r"(r1), "=r"(r2), "=r"(r3) : "r"(saddr));
}
__device__ __forceinline__ void cp_async16(uint32_t saddr, const void* gptr) {
    asm volatile("cp.async.cg.shared.global [%0], [%1], 16;" :: "r"(saddr), "l"(gptr));
}
__device__ __forceinline__ void cp_commit() {
    asm volatile("cp.async.commit_group;");
}
template <int N>
__device__ __forceinline__ void cp_wait() {
    asm volatile("cp.async.wait_group %0;" :: "n"(N));
}

// ----------------------------------------------------------------------------
// Merged pack kernel: x -> fp16, both weights -> k-pair-packed fp16,
// resets the QKV work-queue counter.
// ----------------------------------------------------------------------------
#define PK_X   (8192 * 256 / 4)
#define PK_WQ  (128 * (C3_ / 4))
#define PK_WP  (128 * (C_ / 4))
#define PK_TOT (PK_X + PK_WQ + PK_WP)

__global__ void pack_all(const float* __restrict__ x,
                         const float* __restrict__ wq,
                         const float* __restrict__ wp,
                         uint32_t* __restrict__ x16,
                         uint32_t* __restrict__ wq16,
                         uint32_t* __restrict__ wp16)
{
    int i = blockIdx.x * blockDim.x + threadIdx.x;
    if (i == 0) { g_ctr[0] = 0; g_ctr[1] = 0; }
    if (i < PK_X) {
        float4 v = ((const float4*)x)[i];
        uint2 o; o.x = pack_f16x2(v.x, v.y); o.y = pack_f16x2(v.z, v.w);
        ((uint2*)x16)[i] = o;
    } else if (i < PK_X + PK_WQ) {
        int j = i - PK_X;
        int n4 = C3_ >> 2;
        int kp = j / n4, c4 = (j - kp * n4) * 4;
        float4 a = *(const float4*)&wq[(size_t)(2 * kp) * C3_ + c4];
        float4 b = *(const float4*)&wq[(size_t)(2 * kp + 1) * C3_ + c4];
        uint4 o;
        o.x = pack_f16x2(a.x, b.x); o.y = pack_f16x2(a.y, b.y);
        o.z = pack_f16x2(a.z, b.z); o.w = pack_f16x2(a.w, b.w);
        *(uint4*)&wq16[(size_t)kp * C3_ + c4] = o;
    } else if (i < PK_TOT) {
        int j = i - PK_X - PK_WQ;
        int n4 = C_ >> 2;
        int kp = j / n4, c4 = (j - kp * n4) * 4;
        float4 a = *(const float4*)&wp[(size_t)(2 * kp) * C_ + c4];
        float4 b = *(const float4*)&wp[(size_t)(2 * kp + 1) * C_ + c4];
        uint4 o;
        o.x = pack_f16x2(a.x, b.x); o.y = pack_f16x2(a.y, b.y);
        o.z = pack_f16x2(a.z, b.z); o.w = pack_f16x2(a.w, b.w);
        *(uint4*)&wp16[(size_t)kp * C_ + c4] = o;
    }
}

// ----------------------------------------------------------------------------
// QKV GEMM: persistent fp16 tensor-core, 128x128 tiles, BK=32, 3-stage
// cp.async, ldmatrix A-frags (R16, measured ~19 us). fp16 out, q pre-scaled.
// ----------------------------------------------------------------------------
#define AST 20
#define WST 136
#define GA_WORDS (128 * AST)
#define GW_WORDS (16 * WST)
#define GSTAGES 3
#define GEMM_SMEM_BYTES (GSTAGES * (GA_WORDS + GW_WORDS) * 4)

__global__ __launch_bounds__(256, 2)
void gemm16_qkv_kernel(const uint32_t* __restrict__ Apk,
                       const uint32_t* __restrict__ Wpk,
                       const float* __restrict__ bias,
                       uint32_t* __restrict__ o16,
                       int M, int N, int K, float qsc, int nTiles)
{
    extern __shared__ uint32_t gsm[];
    uint32_t* Asm = gsm;
    uint32_t* Wsm = gsm + GSTAGES * GA_WORDS;
    __shared__ uint32_t s_tile;

    const int tid  = threadIdx.x;
    const int wid  = tid >> 5;
    const int lane = tid & 31;
    const int g    = lane >> 2;
    const int tg   = lane & 3;
    const int lm   = lane >> 3;
    const int lr   = lane & 7;
    const int wm   = wid & 1;
    const int wn   = wid >> 1;

    const int Kp2 = K >> 1;
    const int nTilesX = N >> 7;

    const int a_row = tid >> 1;
    const int a_seg = (tid & 1) * 8;
    const int w_row = tid >> 4;
    const int w_seg = (tid & 15) * 8;

    const uint32_t sA = (uint32_t)__cvta_generic_to_shared(Asm);
    const uint32_t sW = (uint32_t)__cvta_generic_to_shared(Wsm);

    const uint32_t afrag_base =
        (uint32_t)((((lm & 1) * 8 + lr) * AST + (lm >> 1) * 4) * 4);

    const int nChunks = K >> 5;

    for (;;) {
        __syncthreads();
        if (tid == 0) s_tile = atomicAdd(&g_ctr[0], 1u);
        __syncthreads();
        const int t = (int)s_tile;
        if (t >= nTiles) break;

        const int bm = (t / nTilesX) * 128;
        const int bn = (t % nTilesX) * 128;

        auto prefetch = [&](int st, int c) {
            const uint32_t sa = sA + (uint32_t)st * GA_WORDS * 4;
            const uint32_t sw = sW + (uint32_t)st * GW_WORDS * 4;
            const int kp0 = c * 16;
            cp_async16(sa + (uint32_t)(a_row * AST + a_seg) * 4,
                       Apk + (size_t)(bm + a_row) * Kp2 + kp0 + a_seg);
            cp_async16(sa + (uint32_t)(a_row * AST + a_seg + 4) * 4,
                       Apk + (size_t)(bm + a_row) * Kp2 + kp0 + a_seg + 4);
            cp_async16(sw + (uint32_t)(w_row * WST + w_seg) * 4,
                       Wpk + (size_t)(kp0 + w_row) * N + bn + w_seg);
            cp_async16(sw + (uint32_t)(w_row * WST + w_seg + 4) * 4,
                       Wpk + (size_t)(kp0 + w_row) * N + bn + w_seg + 4);
        };

        float acc[4][4][4];
#pragma unroll
        for (int r = 0; r < 4; r++)
#pragma unroll
            for (int c = 0; c < 4; c++)
#pragma unroll
                for (int i = 0; i < 4; i++) acc[r][c][i] = 0.f;

        prefetch(0, 0); cp_commit();
        prefetch(1, 1); cp_commit();

        for (int ch = 0; ch < nChunks; ch++) {
            if (ch + 1 < nChunks) cp_wait<1>(); else cp_wait<0>();
            __syncthreads();
            if (ch + 2 < nChunks) {
                prefetch((ch + 2) % GSTAGES, ch + 2);
                cp_commit();
            }

            const uint32_t Ab_s = sA + (uint32_t)((ch % GSTAGES) * GA_WORDS) * 4;
            const uint32_t* Wb = Wsm + (ch % GSTAGES) * GW_WORDS;

#pragma unroll
            for (int kk = 0; kk < 2; kk++) {
                uint32_t a[4][4];
#pragma unroll
                for (int r = 0; r < 4; r++) {
                    ldm_x4(a[r][0], a[r][1], a[r][2], a[r][3],
                           Ab_s + afrag_base
                                + (uint32_t)(((wm * 64 + r * 16) * AST + kk * 8) * 4));
                }
                uint32_t bfr[4][2];
#pragma unroll
                for (int c = 0; c < 4; c++) {
                    const int col = wn * 32 + c * 8 + g;
                    bfr[c][0] = Wb[(kk * 8 + tg)     * WST + col];
                    bfr[c][1] = Wb[(kk * 8 + tg + 4) * WST + col];
                }
#pragma unroll
                for (int r = 0; r < 4; r++)
#pragma unroll
                    for (int c = 0; c < 4; c++)
                        mma_f16(acc[r][c][0], acc[r][c][1], acc[r][c][2], acc[r][c][3],
                                a[r][0], a[r][1], a[r][2], a[r][3], bfr[c][0], bfr[c][1]);
            }
            __syncthreads();
        }

#pragma unroll
        for (int r = 0; r < 4; r++) {
            const int row0 = bm + wm * 64 + r * 16 + g;
#pragma unroll
            for (int c = 0; c < 4; c++) {
                const int col = bn + wn * 32 + c * 8 + 2 * tg;
                const float2 bb = *(const float2*)&bias[col];
                const float sc = (col < C_) ? qsc : 1.f;
                float v0 = (acc[r][c][0] + bb.x) * sc, v1 = (acc[r][c][1] + bb.y) * sc;
                float v2 = (acc[r][c][2] + bb.x) * sc, v3 = (acc[r][c][3] + bb.y) * sc;
                o16[(size_t)row0       * (N >> 1) + (col >> 1)] = pack_f16x2(v0, v1);
                o16[(size_t)(row0 + 8) * (N >> 1) + (col >> 1)] = pack_f16x2(v2, v3);
            }
        }
    }
}

// ----------------------------------------------------------------------------
// Projection GEMM: BN=64 variant (R15 verbatim, MODE 0) — 256 blocks so every
// SM is covered (the 128x128 version starves 20 SMs). fp32 out.
// ----------------------------------------------------------------------------
#define PWST 72         // 72 % 32 == 8 -> B-frag banks (8tg+g)%32 conflict-free
#define PGW_WORDS (16 * PWST)
#define PROJ_SMEM_BYTES (GSTAGES * (GA_WORDS + PGW_WORDS) * 4)

__global__ __launch_bounds__(256, 2)
void gemm16_proj_kernel(const uint32_t* __restrict__ Apk,
                        const uint32_t* __restrict__ Wpk,
                        const float* __restrict__ bias,
                        float* __restrict__ o32,
                        int M, int N, int K)
{
    extern __shared__ uint32_t gsm[];
    uint32_t* Asm = gsm;
    uint32_t* Wsm = gsm + GSTAGES * GA_WORDS;

    const int tid  = threadIdx.x;
    const int wid  = tid >> 5;
    const int lane = tid & 31;
    const int g    = lane >> 2;
    const int tg   = lane & 3;
    const int lm   = lane >> 3;
    const int lr   = lane & 7;
    const int wm   = wid & 3;       // 4 m-warps (32 rows each)
    const int wn   = wid >> 2;      // 2 n-warps (32 cols each)

    const int bm = blockIdx.y * 128;
    const int bn = blockIdx.x * 64;
    const int Kp2 = K >> 1;

    const int a_row = tid >> 1;
    const int a_seg = (tid & 1) * 8;
    const int w_row = tid >> 4;
    const int w_seg = (tid & 15) * 4;

    const uint32_t sA = (uint32_t)__cvta_generic_to_shared(Asm);
    const uint32_t sW = (uint32_t)__cvta_generic_to_shared(Wsm);

    const uint32_t afrag_base =
        (uint32_t)((((lm & 1) * 8 + lr) * AST + (lm >> 1) * 4) * 4);

    const int nChunks = K >> 5;

    auto prefetch = [&](int st, int c) {
        const uint32_t sa = sA + (uint32_t)st * GA_WORDS * 4;
        const uint32_t sw = sW + (uint32_t)st * PGW_WORDS * 4;
        const int kp0 = c * 16;
        cp_async16(sa + (uint32_t)(a_row * AST + a_seg) * 4,
                   Apk + (size_t)(bm + a_row) * Kp2 + kp0 + a_seg);
        cp_async16(sa + (uint32_t)(a_row * AST + a_seg + 4) * 4,
                   Apk + (size_t)(bm + a_row) * Kp2 + kp0 + a_seg + 4);
        cp_async16(sw + (uint32_t)(w_row * PWST + w_seg) * 4,
                   Wpk + (size_t)(kp0 + w_row) * N + bn + w_seg);
    };

    float acc[2][4][4];
#pragma unroll
    for (int r = 0; r < 2; r++)
#pragma unroll
        for (int c = 0; c < 4; c++)
#pragma unroll
            for (int i = 0; i < 4; i++) acc[r][c][i] = 0.f;

    prefetch(0, 0); cp_commit();
    prefetch(1, 1); cp_commit();

    for (int ch = 0; ch < nChunks; ch++) {
        if (ch + 1 < nChunks) cp_wait<1>(); else cp_wait<0>();
        __syncthreads();
        if (ch + 2 < nChunks) {
            prefetch((ch + 2) % GSTAGES, ch + 2);
            cp_commit();
        }

        const uint32_t Ab_s = sA + (uint32_t)((ch % GSTAGES) * GA_WORDS) * 4;
        const uint32_t* Wb = Wsm + (ch % GSTAGES) * PGW_WORDS;

#pragma unroll
        for (int kk = 0; kk < 2; kk++) {
            uint32_t a[2][4];
#pragma unroll
            for (int r = 0; r < 2; r++) {
                ldm_x4(a[r][0], a[r][1], a[r][2], a[r][3],
                       Ab_s + afrag_base
                            + (uint32_t)(((wm * 32 + r * 16) * AST + kk * 8) * 4));
            }
            uint32_t bfr[4][2];
#pragma unroll
            for (int c = 0; c < 4; c++) {
                const int col = wn * 32 + c * 8 + g;
                bfr[c][0] = Wb[(kk * 8 + tg)     * PWST + col];
                bfr[c][1] = Wb[(kk * 8 + tg + 4) * PWST + col];
            }
#pragma unroll
            for (int r = 0; r < 2; r++)
#pragma unroll
                for (int c = 0; c < 4; c++)
                    mma_f16(acc[r][c][0], acc[r][c][1], acc[r][c][2], acc[r][c][3],
                            a[r][0], a[r][1], a[r][2], a[r][3], bfr[c][0], bfr[c][1]);
        }
    }

#pragma unroll
    for (int r = 0; r < 2; r++) {
        const int row0 = bm + wm * 32 + r * 16 + g;
#pragma unroll
        for (int c = 0; c < 4; c++) {
            const int col = bn + wn * 32 + c * 8 + 2 * tg;
            const float2 bb = *(const float2*)&bias[col];
            *(float2*)&o32[(size_t)row0 * N + col] =
                make_float2(acc[r][c][0] + bb.x, acc[r][c][1] + bb.y);
            *(float2*)&o32[(size_t)(row0 + 8) * N + col] =
                make_float2(acc[r][c][2] + bb.x, acc[r][c][3] + bb.y);
        }
    }
}

// ----------------------------------------------------------------------------
// Causal flash attention — R12 version verbatim.
// ----------------------------------------------------------------------------
#define QST 20
#define ATT_TILE (64 * QST)
#define ATTN_SMEM_BYTES (5 * ATT_TILE * 4)
#define ONES_H2 0x3C003C00u

__global__ __launch_bounds__(128, 4)
void attn_kernel(const uint32_t* __restrict__ qkv, uint32_t* __restrict__ yout)
{
    extern __shared__ uint32_t sm[];
    uint32_t* Qp = sm;
    uint32_t* Kp = sm + ATT_TILE;
    uint32_t* Vp = Kp + 2 * ATT_TILE;

    const int tid  = threadIdx.x;
    const int wid  = tid >> 5;
    const int lane = tid & 31;
    const int g    = lane >> 2;
    const int tg   = lane & 3;
    const int lm   = lane >> 3;
    const int lr   = lane & 7;

    const int qt = gridDim.x - 1 - blockIdx.x;
    const int q0 = qt * 64;
    const int bh = blockIdx.y;
    const int b  = bh >> 3;
    const int h  = bh & 7;

    const uint32_t sQ = (uint32_t)__cvta_generic_to_shared(Qp);
    const uint32_t sK = (uint32_t)__cvta_generic_to_shared(Kp);
    const uint32_t sV = (uint32_t)__cvta_generic_to_shared(Vp);

    const uint32_t kfrag_base =
        (uint32_t)(((((lm >> 1) * 8) + lr) * QST + (lm & 1) * 4) * 4);
    const uint32_t vfrag_base =
        (uint32_t)(((((lm & 1) * 8) + lr) * QST + (lm >> 1) * 4) * 4);

    const uint32_t* base = qkv + (size_t)(b * T_) * 384;

    auto prefetch_kv = [&](int buf, int kt) {
#pragma unroll
        for (int it = 0; it < 4; it++) {
            const int idx  = tid + it * 128;
            const int half = idx >> 8;
            const int row  = (idx & 255) >> 2;
            const int seg  = (idx & 3) * 4;
            const uint32_t dst = (half ? sV : sK) + (uint32_t)buf * ATT_TILE * 4
                               + (uint32_t)(row * QST + seg) * 4;
            cp_async16(dst, base + (size_t)(kt * 64 + row) * 384
                            + 128 + half * 128 + h * 16 + seg);
        }
    };

#pragma unroll
    for (int it = 0; it < 2; it++) {
        const int idx = tid + it * 128;
        const int row = idx >> 2, seg = (idx & 3) * 4;
        cp_async16(sQ + (uint32_t)(row * QST + seg) * 4,
                   base + (size_t)(q0 + row) * 384 + h * 16 + seg);
    }
    prefetch_kv(0, 0);
    cp_commit();
    cp_wait<0>();
    __syncthreads();

    uint32_t qa[2][4];
    {
        const int r0 = wid * 16;
#pragma unroll
        for (int kk = 0; kk < 2; kk++) {
            qa[kk][0] = Qp[(r0 + g)     * QST + kk * 8 + tg];
            qa[kk][1] = Qp[(r0 + g + 8) * QST + kk * 8 + tg];
            qa[kk][2] = Qp[(r0 + g)     * QST + kk * 8 + tg + 4];
            qa[kk][3] = Qp[(r0 + g + 8) * QST + kk * 8 + tg + 4];
        }
    }

    float o_[4][4];
#pragma unroll
    for (int nt = 0; nt < 4; nt++)
#pragma unroll
        for (int c = 0; c < 4; c++) o_[nt][c] = 0.f;
    float la0 = 0.f, la1 = 0.f, la2 = 0.f, la3 = 0.f;

    const int nkt = qt + 1;
    for (int kt = 0; kt < nkt; kt++) {
        if (kt > 0) { cp_wait<0>(); __syncthreads(); }
        if (kt + 1 < nkt) {
            prefetch_kv((kt + 1) & 1, kt + 1);
            cp_commit();
        }

        const uint32_t kT = sK + (uint32_t)((kt & 1) * ATT_TILE) * 4 + kfrag_base;
        const uint32_t vT = sV + (uint32_t)((kt & 1) * ATT_TILE) * 4 + vfrag_base;

        float s[8][4];
#pragma unroll
        for (int nt = 0; nt < 8; nt++)
#pragma unroll
            for (int c = 0; c < 4; c++) s[nt][c] = 0.f;

#pragma unroll
        for (int kk = 0; kk < 2; kk++) {
#pragma unroll
            for (int np = 0; np < 4; np++) {
                uint32_t b0, b1, b2, b3;
                ldm_x4(b0, b1, b2, b3,
                       kT + (uint32_t)(((np * 16) * QST + kk * 8) * 4));
                mma_f16(s[2 * np][0], s[2 * np][1], s[2 * np][2], s[2 * np][3],
                        qa[kk][0], qa[kk][1], qa[kk][2], qa[kk][3], b0, b1);
                mma_f16(s[2 * np + 1][0], s[2 * np + 1][1],
                        s[2 * np + 1][2], s[2 * np + 1][3],
                        qa[kk][0], qa[kk][1], qa[kk][2], qa[kk][3], b2, b3);
            }
        }

        if (kt == nkt - 1) {
            const int r0 = wid * 16 + g;
#pragma unroll
            for (int nt = 0; nt < 8; nt++) {
                const int col0 = nt * 8 + 2 * tg;
                if (col0     > r0)     s[nt][0] = -1e30f;
                if (col0 + 1 > r0)     s[nt][1] = -1e30f;
                if (col0     > r0 + 8) s[nt][2] = -1e30f;
                if (col0 + 1 > r0 + 8) s[nt][3] = -1e30f;
            }
        }

        uint32_t pa[4][4];
#pragma unroll
        for (int nt = 0; nt < 8; nt++) {
            pa[nt >> 1][(nt & 1) * 2]     = ex2_h2(pack_f16x2(s[nt][0], s[nt][1]));
            pa[nt >> 1][(nt & 1) * 2 + 1] = ex2_h2(pack_f16x2(s[nt][2], s[nt][3]));
        }

#pragma unroll
        for (int kb = 0; kb < 4; kb++)
            mma_f16(la0, la1, la2, la3,
                    pa[kb][0], pa[kb][1], pa[kb][2], pa[kb][3], ONES_H2, ONES_H2);

#pragma unroll
        for (int kb = 0; kb < 4; kb++) {
#pragma unroll
            for (int np = 0; np < 2; np++) {
                uint32_t v0, v1, v2, v3;
                ldm_x4t(v0, v1, v2, v3,
                        vT + (uint32_t)(((kb * 16) * QST + np * 8) * 4));
                mma_f16(o_[2 * np][0], o_[2 * np][1], o_[2 * np][2], o_[2 * np][3],
                        pa[kb][0], pa[kb][1], pa[kb][2], pa[kb][3], v0, v1);
                mma_f16(o_[2 * np + 1][0], o_[2 * np + 1][1],
                        o_[2 * np + 1][2], o_[2 * np + 1][3],
                        pa[kb][0], pa[kb][1], pa[kb][2], pa[kb][3], v2, v3);
            }
        }
    }

    const float i0 = 1.f / la0;
    const float i1 = 1.f / la2;
    uint32_t* yo  = yout + (size_t)(b * T_ + q0 + wid * 16 + g) * 128 + h * 16;
    uint32_t* yo8 = yo + (size_t)8 * 128;
#pragma unroll
    for (int nt = 0; nt < 4; nt++) {
        yo [nt * 4 + tg] = pack_f16x2(o_[nt][0] * i0, o_[nt][1] * i0);
        yo8[nt * 4 + tg] = pack_f16x2(o_[nt][2] * i1, o_[nt][3] * i1);
    }
}

// ----------------------------------------------------------------------------
extern "C" void kernel_launch(void* const* d_in, const int* in_sizes, int n_in,
                              void* d_out, int out_size)
{
    const float* x      = (const float*)d_in[0];
    const float* w_qkv  = (const float*)d_in[1];
    const float* b_qkv  = (const float*)d_in[2];
    const float* w_proj = (const float*)d_in[3];
    const float* b_proj = (const float*)d_in[4];
    float* out = (float*)d_out;

    uint32_t *x16, *wqkv16, *wp16, *qkv16, *y16;
    cudaGetSymbolAddress((void**)&x16,    g_x16u);
    cudaGetSymbolAddress((void**)&wqkv16, g_wqkv16u);
    cudaGetSymbolAddress((void**)&wp16,   g_wp16u);
    cudaGetSymbolAddress((void**)&qkv16,  g_qkv16u);
    cudaGetSymbolAddress((void**)&y16,    g_y16u);

    const int M = B_ * T_;    // 8192
    const float qsc = 0.17677669529663687f * 1.4426950408889634f;

    cudaFuncSetAttribute(gemm16_qkv_kernel,
                         cudaFuncAttributeMaxDynamicSharedMemorySize, GEMM_SMEM_BYTES);
    cudaFuncSetAttribute(gemm16_proj_kernel,
                         cudaFuncAttributeMaxDynamicSharedMemorySize, PROJ_SMEM_BYTES);
    cudaFuncSetAttribute(attn_kernel,
                         cudaFuncAttributeMaxDynamicSharedMemorySize, ATTN_SMEM_BYTES);

    // 0) merged pack + work-queue reset
    pack_all<<<(PK_TOT + 255) / 256, 256>>>(x, w_qkv, w_proj, x16, wqkv16, wp16);

    // 1) QKV GEMM (persistent; 384 tiles of 128x128)
    {
        const int nTiles = (M / 128) * (C3_ / 128);      // 384
        gemm16_qkv_kernel<<<296, 256, GEMM_SMEM_BYTES>>>(
            x16, wqkv16, b_qkv, qkv16, M, C3_, C_, qsc, nTiles);
    }

    // 2) Causal attention (R12 config)
    {
        dim3 grid(T_ / 64, B_ * H_);
        attn_kernel<<<grid, 128, ATTN_SMEM_BYTES>>>(qkv16, y16);
    }

    // 3) Projection GEMM (BN=64, 256 blocks -> full SM coverage) -> d_out
    {
        dim3 grid(C_ / 64, M / 128);                     // 4 x 64 = 256
        gemm16_proj_kernel<<<grid, 256, PROJ_SMEM_BYTES>>>(
            y16, wp16, b_proj, out, M, C_, C_);
    }
}